// round 7
// baseline (speedup 1.0000x reference)
#include <cuda_runtime.h>
#include <cuda_fp16.h>
#include <cstdint>

#define NN   12288
#define KK   32
#define DD   128

typedef unsigned long long ull;

// Scratch: G = raw_features @ W_lin^T, fp16 (N x 128, 3.15 MB)
__device__ __align__(16) __half g_Gh[NN * DD];
// Scratch: masked gather weights w[b][k] (1.5 MB), produced by the GEMM kernel
__device__ __align__(16) float  g_w[NN * KK];

// ---------------------------------------------------------------------------
// packed f32x2 helpers
// ---------------------------------------------------------------------------
__device__ __forceinline__ ull pack_dup(float x) {
    ull r;
    asm("mov.b64 %0, {%1, %1};" : "=l"(r) : "f"(x));
    return r;
}
__device__ __forceinline__ void fma2(ull& d, ull a, ull b) {
    asm("fma.rn.f32x2 %0, %1, %2, %0;" : "+l"(d) : "l"(a), "l"(b));
}
__device__ __forceinline__ void unpack2(float& lo, float& hi, ull v) {
    asm("mov.b64 {%0, %1}, %2;" : "=f"(lo), "=f"(hi) : "l"(v));
}

// ---------------------------------------------------------------------------
// Kernel 1: G = F @ W^T (fp16 out)  +  fused w-prep:
//   g_w[b][k] = (nb==nodes[b]) ? 0 : reweighted[nodes[b]][nb]
// The w-prep loads (3-deep random chain, ~DRAM latency) are issued BEFORE the
// FFMA mainloop and stored AFTER it — latency fully hidden under compute.
// Grid (192,2) = 384 CTAs x 128 thr; each CTA preps 1024 w entries (8/thread).
// ---------------------------------------------------------------------------
__global__ void __launch_bounds__(128, 3)
gemm_G_kernel(const float* __restrict__ F, const float* __restrict__ W,
              const int* __restrict__ nodes, const int* __restrict__ neighbors,
              const float* __restrict__ rew)
{
    extern __shared__ float sm[];
    float* Fst = sm;                 // 128 * 66  (Fst[k*66 + m])
    float* Wt  = sm + 128 * 66;      // 128 * 66  (Wt [k*66 + n])

    const int tid = threadIdx.x;
    const int bm  = blockIdx.x;
    const int bn  = blockIdx.y;
    const int bid = blockIdx.y * 192 + blockIdx.x;

    // ---- fused w-prep: issue the random loads now, store after mainloop ----
    const int wbase = bid * 1024 + tid;
    float w8[8];
    #pragma unroll
    for (int i = 0; i < 8; i++) {
        const int idx  = wbase + i * 128;
        const int b    = idx >> 5;
        const int node = __ldg(&nodes[b]);
        const int nb   = __ldg(&neighbors[idx]);
        float w = 0.0f;
        if (nb != node)
            w = __ldg(&rew[(size_t)node * NN + nb]);
        w8[i] = w;
    }

    // ---- stage GEMM tiles ----
    const float* Fblk = F + (size_t)bm * 64 * DD;
    const float* Wblk = W + (size_t)bn * 64 * DD;
    #pragma unroll 8
    for (int idx = tid; idx < 64 * 128; idx += 128) {
        int r = idx >> 7, k = idx & 127;
        Fst[k * 66 + r] = Fblk[idx];
        Wt [k * 66 + r] = Wblk[idx];
    }
    __syncthreads();

    const int tx = tid & 15;   // cols 4*tx .. 4*tx+3
    const int ty = tid >> 4;   // rows 8*ty .. 8*ty+7

    ull acc[4][4];
    #pragma unroll
    for (int p = 0; p < 4; p++)
        #pragma unroll
        for (int c = 0; c < 4; c++)
            acc[p][c] = 0ULL;

    #pragma unroll 4
    for (int kk = 0; kk < 128; kk++) {
        const float* fr = &Fst[kk * 66 + 8 * ty];
        ull a2[4];
        #pragma unroll
        for (int p = 0; p < 4; p++)
            a2[p] = *reinterpret_cast<const ull*>(&fr[2 * p]);

        float2 b01 = *reinterpret_cast<const float2*>(&Wt[kk * 66 + 4 * tx]);
        float2 b23 = *reinterpret_cast<const float2*>(&Wt[kk * 66 + 4 * tx + 2]);
        ull bd[4];
        bd[0] = pack_dup(b01.x); bd[1] = pack_dup(b01.y);
        bd[2] = pack_dup(b23.x); bd[3] = pack_dup(b23.y);

        #pragma unroll
        for (int p = 0; p < 4; p++)
            #pragma unroll
            for (int c = 0; c < 4; c++)
                fma2(acc[p][c], a2[p], bd[c]);
    }

    // ---- store w-prep results (loads have long completed) ----
    #pragma unroll
    for (int i = 0; i < 8; i++)
        g_w[wbase + i * 128] = w8[i];

    // ---- epilogue: fp16 G ----
    float v[8][4];
    #pragma unroll
    for (int p = 0; p < 4; p++)
        #pragma unroll
        for (int c = 0; c < 4; c++) {
            float lo, hi;
            unpack2(lo, hi, acc[p][c]);
            v[2 * p][c]     = lo;
            v[2 * p + 1][c] = hi;
        }

    const int gm0 = bm * 64 + 8 * ty;
    const int gn0 = bn * 64 + 4 * tx;
    #pragma unroll
    for (int r = 0; r < 8; r++) {
        __half2 h01 = __floats2half2_rn(v[r][0], v[r][1]);
        __half2 h23 = __floats2half2_rn(v[r][2], v[r][3]);
        uint2 st;
        st.x = *reinterpret_cast<unsigned*>(&h01);
        st.y = *reinterpret_cast<unsigned*>(&h23);
        *reinterpret_cast<uint2*>(&g_Gh[(size_t)(gm0 + r) * DD + gn0]) = st;
    }
}

// ---------------------------------------------------------------------------
// Kernel 2: out[b][d] = relu( sum_k w[b][k] * G[nb[b][k]][d] + bias[d] )
// 256 thr = 8 warps = 16 nodes/block. Warp handles 2 nodes: lanes 0-15 node A,
// lanes 16-31 node B; each lane owns 8 columns (one LDG.128 of fp16 per k).
// w comes precomputed from g_w (coalesced); k unrolled by 4 (4 LDG.128 in
// flight per warp). fp32 accumulate.
// ---------------------------------------------------------------------------
__global__ void __launch_bounds__(256)
gather_kernel(const int* __restrict__ neighbors,
              const float* __restrict__ b_lin,
              float* __restrict__ out)
{
    __shared__ int   nb_s[16][KK];
    __shared__ float w_s [16][KK];

    const int tid = threadIdx.x;
    const int b0  = blockIdx.x * 16;

    // Stage: 16 nodes x 32 k = 512 entries, 2 per thread (coalesced)
    #pragma unroll
    for (int i = 0; i < 2; i++) {
        const int e  = tid + i * 256;
        const int ln = e >> 5;
        const int k  = e & 31;
        const int gi = (b0 + ln) * KK + k;
        nb_s[ln][k] = neighbors[gi];
        w_s [ln][k] = g_w[gi];
    }
    __syncthreads();

    const int lane = tid & 31;
    const int ln2  = ((tid >> 5) << 1) | (lane >> 4);  // local node 0..15
    const int col  = (lane & 15) * 8;                  // 8 cols per lane
    const int b    = b0 + ln2;

    float acc[8];
    #pragma unroll
    for (int i = 0; i < 8; i++) acc[i] = 0.0f;

    #pragma unroll
    for (int kb = 0; kb < KK; kb += 4) {
        uint4 g[4];
        float wv[4];
        #pragma unroll
        for (int u = 0; u < 4; u++) {
            const int nb = nb_s[ln2][kb + u];
            wv[u] = w_s[ln2][kb + u];
            g[u]  = __ldg(reinterpret_cast<const uint4*>(
                              &g_Gh[(size_t)nb * DD + col]));
        }
        #pragma unroll
        for (int u = 0; u < 4; u++) {
            float2 f0 = __half22float2(*reinterpret_cast<__half2*>(&g[u].x));
            float2 f1 = __half22float2(*reinterpret_cast<__half2*>(&g[u].y));
            float2 f2 = __half22float2(*reinterpret_cast<__half2*>(&g[u].z));
            float2 f3 = __half22float2(*reinterpret_cast<__half2*>(&g[u].w));
            acc[0] = fmaf(wv[u], f0.x, acc[0]);
            acc[1] = fmaf(wv[u], f0.y, acc[1]);
            acc[2] = fmaf(wv[u], f1.x, acc[2]);
            acc[3] = fmaf(wv[u], f1.y, acc[3]);
            acc[4] = fmaf(wv[u], f2.x, acc[4]);
            acc[5] = fmaf(wv[u], f2.y, acc[5]);
            acc[6] = fmaf(wv[u], f3.x, acc[6]);
            acc[7] = fmaf(wv[u], f3.y, acc[7]);
        }
    }

    const float4 bias0 = __ldg(reinterpret_cast<const float4*>(&b_lin[col]));
    const float4 bias1 = __ldg(reinterpret_cast<const float4*>(&b_lin[col + 4]));
    float4 o0, o1;
    o0.x = fmaxf(acc[0] + bias0.x, 0.f);
    o0.y = fmaxf(acc[1] + bias0.y, 0.f);
    o0.z = fmaxf(acc[2] + bias0.z, 0.f);
    o0.w = fmaxf(acc[3] + bias0.w, 0.f);
    o1.x = fmaxf(acc[4] + bias1.x, 0.f);
    o1.y = fmaxf(acc[5] + bias1.y, 0.f);
    o1.z = fmaxf(acc[6] + bias1.z, 0.f);
    o1.w = fmaxf(acc[7] + bias1.w, 0.f);
    float* op = &out[(size_t)b * DD + col];
    *reinterpret_cast<float4*>(op)     = o0;
    *reinterpret_cast<float4*>(op + 4) = o1;
}

// ---------------------------------------------------------------------------
// Launch. Inputs: nodes(i32 N), neighbors(i32 N*K), raw_features(f32 N*128),
//                 reweighted(f32 N*N), W_lin(f32 128*128), b_lin(f32 128)
// ---------------------------------------------------------------------------
extern "C" void kernel_launch(void* const* d_in, const int* in_sizes, int n_in,
                              void* d_out, int out_size)
{
    const int*   nodes      = (const int*)  d_in[0];
    const int*   neighbors  = (const int*)  d_in[1];
    const float* raw_feats  = (const float*)d_in[2];
    const float* reweighted = (const float*)d_in[3];
    const float* W_lin      = (const float*)d_in[4];
    const float* b_lin      = (const float*)d_in[5];
    float*       out        = (float*)d_out;

    const int smem = 2 * 128 * 66 * (int)sizeof(float);  // 67584 B
    static bool attr_set = false;
    if (!attr_set) {
        cudaFuncSetAttribute(gemm_G_kernel,
                             cudaFuncAttributeMaxDynamicSharedMemorySize, smem);
        attr_set = true;
    }

    dim3 ggrid(NN / 64, DD / 64);
    gemm_G_kernel<<<ggrid, 128, smem>>>(raw_feats, W_lin,
                                        nodes, neighbors, reweighted);
    gather_kernel<<<NN / 16, 256>>>(neighbors, b_lin, out);
}

// round 8
// speedup vs baseline: 1.1792x; 1.1792x over previous
#include <cuda_runtime.h>
#include <cuda_fp16.h>
#include <cstdint>

#define NN   12288
#define KK   32
#define DD   128

typedef unsigned long long ull;

// Scratch: G = raw_features @ W_lin^T, fp16 (N x 128, 3.15 MB)
__device__ __align__(16) __half g_Gh[NN * DD];

// ---------------------------------------------------------------------------
// packed f32x2 helpers
// ---------------------------------------------------------------------------
__device__ __forceinline__ ull pack_dup(float x) {
    ull r;
    asm("mov.b64 %0, {%1, %1};" : "=l"(r) : "f"(x));
    return r;
}
__device__ __forceinline__ void fma2(ull& d, ull a, ull b) {
    asm("fma.rn.f32x2 %0, %1, %2, %0;" : "+l"(d) : "l"(a), "l"(b));
}
__device__ __forceinline__ void unpack2(float& lo, float& hi, ull v) {
    asm("mov.b64 {%0, %1}, %2;" : "=f"(lo), "=f"(hi) : "l"(v));
}

// ---------------------------------------------------------------------------
// Kernel 1: G = F @ W^T (fp16 out). Clean (no fused work).
// Grid (192,2): 64x64 tiles, 128 threads, 3 CTAs/SM.
// Microtile 8 rows x 4 cols, accumulators paired over rows (FFMA2).
// ---------------------------------------------------------------------------
__global__ void __launch_bounds__(128, 3)
gemm_G_kernel(const float* __restrict__ F, const float* __restrict__ W)
{
    extern __shared__ float sm[];
    float* Fst = sm;                 // 128 * 66  (Fst[k*66 + m])
    float* Wt  = sm + 128 * 66;      // 128 * 66  (Wt [k*66 + n])

    const int tid = threadIdx.x;
    const int bm  = blockIdx.x;
    const int bn  = blockIdx.y;

    const float* Fblk = F + (size_t)bm * 64 * DD;
    const float* Wblk = W + (size_t)bn * 64 * DD;

    #pragma unroll 8
    for (int idx = tid; idx < 64 * 128; idx += 128) {
        int r = idx >> 7, k = idx & 127;
        Fst[k * 66 + r] = Fblk[idx];
        Wt [k * 66 + r] = Wblk[idx];
    }
    __syncthreads();

    const int tx = tid & 15;   // cols 4*tx .. 4*tx+3
    const int ty = tid >> 4;   // rows 8*ty .. 8*ty+7

    ull acc[4][4];
    #pragma unroll
    for (int p = 0; p < 4; p++)
        #pragma unroll
        for (int c = 0; c < 4; c++)
            acc[p][c] = 0ULL;

    #pragma unroll 4
    for (int kk = 0; kk < 128; kk++) {
        const float* fr = &Fst[kk * 66 + 8 * ty];
        ull a2[4];
        #pragma unroll
        for (int p = 0; p < 4; p++)
            a2[p] = *reinterpret_cast<const ull*>(&fr[2 * p]);

        float2 b01 = *reinterpret_cast<const float2*>(&Wt[kk * 66 + 4 * tx]);
        float2 b23 = *reinterpret_cast<const float2*>(&Wt[kk * 66 + 4 * tx + 2]);
        ull bd[4];
        bd[0] = pack_dup(b01.x); bd[1] = pack_dup(b01.y);
        bd[2] = pack_dup(b23.x); bd[3] = pack_dup(b23.y);

        #pragma unroll
        for (int p = 0; p < 4; p++)
            #pragma unroll
            for (int c = 0; c < 4; c++)
                fma2(acc[p][c], a2[p], bd[c]);
    }

    float v[8][4];
    #pragma unroll
    for (int p = 0; p < 4; p++)
        #pragma unroll
        for (int c = 0; c < 4; c++) {
            float lo, hi;
            unpack2(lo, hi, acc[p][c]);
            v[2 * p][c]     = lo;
            v[2 * p + 1][c] = hi;
        }

    const int gm0 = bm * 64 + 8 * ty;
    const int gn0 = bn * 64 + 4 * tx;
    #pragma unroll
    for (int r = 0; r < 8; r++) {
        __half2 h01 = __floats2half2_rn(v[r][0], v[r][1]);
        __half2 h23 = __floats2half2_rn(v[r][2], v[r][3]);
        uint2 st;
        st.x = *reinterpret_cast<unsigned*>(&h01);
        st.y = *reinterpret_cast<unsigned*>(&h23);
        *reinterpret_cast<uint2*>(&g_Gh[(size_t)(gm0 + r) * DD + gn0]) = st;
    }
}

// ---------------------------------------------------------------------------
// Kernel 2: out[b][d] = relu( sum_k w[b][k] * G[nb[b][k]][d] + bias[d] )
// One warp per node (12288 warps -> full occupancy). Lane k loads its own
// (nb, w) pair — the random `rew` load is hidden across ~64 resident warps/SM.
// No smem, no barriers. k-loop unrolled by 8: (nb,w) broadcast via shfl,
// 8 uint2 fp16-G loads in flight. fp32 accumulate, lane owns 4 columns.
// ---------------------------------------------------------------------------
__global__ void __launch_bounds__(256)
gather_kernel(const int* __restrict__ nodes,
              const int* __restrict__ neighbors,
              const float* __restrict__ rew,
              const float* __restrict__ b_lin,
              float* __restrict__ out)
{
    const int lane = threadIdx.x & 31;
    const int b    = blockIdx.x * 8 + (threadIdx.x >> 5);

    const int node = __ldg(&nodes[b]);                 // broadcast
    const int nb_l = __ldg(&neighbors[b * KK + lane]); // coalesced
    float w_l = 0.0f;
    if (nb_l != node)
        w_l = __ldg(&rew[(size_t)node * NN + nb_l]);   // random 32B sectors

    const int d4 = lane * 4;                           // 4 fp16 cols -> uint2

    float acc0 = 0.f, acc1 = 0.f, acc2 = 0.f, acc3 = 0.f;

    #pragma unroll
    for (int kb = 0; kb < KK; kb += 8) {
        uint2 g[8];
        float wv[8];
        #pragma unroll
        for (int u = 0; u < 8; u++) {
            const int nbk = __shfl_sync(0xffffffffu, nb_l, kb + u);
            wv[u] = __shfl_sync(0xffffffffu, w_l, kb + u);
            g[u]  = __ldg(reinterpret_cast<const uint2*>(
                              &g_Gh[(size_t)nbk * DD + d4]));
        }
        #pragma unroll
        for (int u = 0; u < 8; u++) {
            float2 lo = __half22float2(*reinterpret_cast<__half2*>(&g[u].x));
            float2 hi = __half22float2(*reinterpret_cast<__half2*>(&g[u].y));
            acc0 = fmaf(wv[u], lo.x, acc0);
            acc1 = fmaf(wv[u], lo.y, acc1);
            acc2 = fmaf(wv[u], hi.x, acc2);
            acc3 = fmaf(wv[u], hi.y, acc3);
        }
    }

    const float4 bias = __ldg(reinterpret_cast<const float4*>(&b_lin[d4]));
    float4 o;
    o.x = fmaxf(acc0 + bias.x, 0.f);
    o.y = fmaxf(acc1 + bias.y, 0.f);
    o.z = fmaxf(acc2 + bias.z, 0.f);
    o.w = fmaxf(acc3 + bias.w, 0.f);
    *reinterpret_cast<float4*>(&out[(size_t)b * DD + d4]) = o;
}

// ---------------------------------------------------------------------------
// Launch. Inputs: nodes(i32 N), neighbors(i32 N*K), raw_features(f32 N*128),
//                 reweighted(f32 N*N), W_lin(f32 128*128), b_lin(f32 128)
// ---------------------------------------------------------------------------
extern "C" void kernel_launch(void* const* d_in, const int* in_sizes, int n_in,
                              void* d_out, int out_size)
{
    const int*   nodes      = (const int*)  d_in[0];
    const int*   neighbors  = (const int*)  d_in[1];
    const float* raw_feats  = (const float*)d_in[2];
    const float* reweighted = (const float*)d_in[3];
    const float* W_lin      = (const float*)d_in[4];
    const float* b_lin      = (const float*)d_in[5];
    float*       out        = (float*)d_out;

    const int smem = 2 * 128 * 66 * (int)sizeof(float);  // 67584 B
    static bool attr_set = false;
    if (!attr_set) {
        cudaFuncSetAttribute(gemm_G_kernel,
                             cudaFuncAttributeMaxDynamicSharedMemorySize, smem);
        attr_set = true;
    }

    dim3 ggrid(NN / 64, DD / 64);
    gemm_G_kernel<<<ggrid, 128, smem>>>(raw_feats, W_lin);
    gather_kernel<<<NN / 8, 256>>>(nodes, neighbors, reweighted, b_lin, out);
}